// round 14
// baseline (speedup 1.0000x reference)
#include <cuda_runtime.h>
#include <cuda_bf16.h>

// Problem constants (fixed by the dataset)
#define BB 16
#define TT 512
#define DD 384
#define D4 (DD / 4)          // 96 float4 per row
#define MAXLEN 4096
#define NTHR 512
#define NWARP (NTHR / 32)    // 16
#define FPBLK 64             // frames per block
#define BPB (MAXLEN / FPBLK) // 64 blocks per batch -> grid = 1024
#define FPW (FPBLK / NWARP)  // 4 frames per warp
#define ITER (D4 / 32)       // 3 float4 per lane per frame

// ---------------------------------------------------------------------------
// Fused kernel (R12 structure, __stcs restored; ONLY change vs R12: all 4 of
// a warp's frames batched at once -> 12 independent LDG.128 in flight, then
// 12 STG.128 (.cs)). Scan + scatter inversion proven across R5-R12.
// ---------------------------------------------------------------------------
__global__ void __launch_bounds__(NTHR)
lr_fused(const float4* __restrict__ x, const int* __restrict__ dur,
         float* __restrict__ out, int mode) {
    __shared__ int wsum[NWARP];
    __shared__ int fidx[FPBLK];   // frame -> token index for this window, -1 = zero
    __shared__ int s_mel;

    const int b    = blockIdx.x / BPB;
    const int blk  = blockIdx.x - b * BPB;
    const int t    = threadIdx.x;
    const int lane = t & 31;
    const int w    = t >> 5;

    // ---- inclusive scan of durations: warp shuffle + warp-total fixup ----
    const int v = __ldg(&dur[b * TT + t]);
    int sc = v;
    #pragma unroll
    for (int o = 1; o < 32; o <<= 1) {
        int n = __shfl_up_sync(0xffffffffu, sc, o);
        if (lane >= o) sc += n;
    }
    if (lane == 31) wsum[w] = sc;
    if (t < FPBLK) fidx[t] = -1;
    __syncthreads();
    if (w == 0 && lane < NWARP) {
        int ws = wsum[lane];
        #pragma unroll
        for (int o = 1; o < NWARP; o <<= 1) {
            int n = __shfl_up_sync(0x0000ffffu, ws, o);
            if (lane >= o) ws += n;
        }
        wsum[lane] = ws;
        if (lane == NWARP - 1) s_mel = ws;   // total = mel_len
    }
    __syncthreads();

    const int end   = sc + (w ? wsum[w - 1] : 0);   // inclusive cum[t]
    const int start = end - v;                       // cum[t-1]
    const int mel   = s_mel;
    const int lim   = mel < MAXLEN ? mel : MAXLEN;
    const int f0    = blk * FPBLK;

    // ---- scatter inversion into this block's window (proven semantics) ----
    {
        const int e2 = end < lim ? end : lim;
        int a  = start > f0 ? start : f0;
        int bd = e2 < (f0 + FPBLK) ? e2 : (f0 + FPBLK);
        for (int f = a; f < bd; ++f) fidx[f - f0] = t;        // durations < 8
    }

    // mel_len tail (output 1), written once per batch by block 0
    if (blk == 0 && t == 0 && mode) {
        const long long base = (long long)BB * MAXLEN * DD;
        if (mode == 1)      out[base + b] = (float)mel;
        else                ((long long*)(out + base))[b] = (long long)mel;
    }
    __syncthreads();

    // ---- gather + streaming store: 4 frames, 12 LDG.128 in flight ----
    const float4* xb = x + (size_t)b * TT * D4;
    float4* ob = (float4*)((float*)out) + ((size_t)b * MAXLEN + f0) * D4;
    const int fr0 = w * FPW;                 // this warp's first frame

    int    id[FPW];
    float4 val[FPW][ITER];
    #pragma unroll
    for (int p = 0; p < FPW; ++p) id[p] = fidx[fr0 + p];   // uniform per warp

    #pragma unroll
    for (int p = 0; p < FPW; ++p) {
        #pragma unroll
        for (int i = 0; i < ITER; ++i) {
            val[p][i] = make_float4(0.f, 0.f, 0.f, 0.f);
            if (id[p] >= 0)
                val[p][i] = __ldg(&xb[id[p] * D4 + lane + 32 * i]);
        }
    }
    #pragma unroll
    for (int p = 0; p < FPW; ++p) {
        #pragma unroll
        for (int i = 0; i < ITER; ++i)
            __stcs(&ob[(fr0 + p) * D4 + lane + 32 * i], val[p][i]);
    }
}

extern "C" void kernel_launch(void* const* d_in, const int* in_sizes, int n_in,
                              void* d_out, int out_size) {
    const float* x   = (const float*)d_in[0];
    const int*   dur = (const int*)d_in[1];   // int32 (JAX x64 disabled)

    const long long base = (long long)BB * MAXLEN * DD;   // 25,165,824 f32
    int mode = 0;
    if ((long long)out_size == base + BB)            mode = 1;  // mel as f32
    else if ((long long)out_size == base + 2 * BB)   mode = 2;  // mel as i64

    lr_fused<<<BB * BPB, NTHR>>>((const float4*)x, dur, (float*)d_out, mode);
}

// round 15
// speedup vs baseline: 1.3972x; 1.3972x over previous
#include <cuda_runtime.h>
#include <cuda_bf16.h>

// Problem constants (fixed by the dataset)
#define BB 16
#define TT 512
#define DD 384
#define D4 (DD / 4)          // 96 float4 per row
#define MAXLEN 4096
#define NTHR 512
#define NWARP (NTHR / 32)    // 16
#define FPBLK 64             // frames per block
#define BPB (MAXLEN / FPBLK) // 64 blocks per batch -> grid = 1024
#define FPW (FPBLK / NWARP)  // 4 frames per warp
#define ITER (D4 / 32)       // 3 float4 per lane per frame

// ---------------------------------------------------------------------------
// FINAL kernel (= R12, the measured optimum at 18.9us):
//  - single fused launch: warp-shuffle inclusive scan of durations,
//    scatter inversion (token t owns frames [cum[t-1], min(cum[t], lim))),
//    then warp-per-frame gather + streaming stores.
//  - gather: warp w owns frames [w*4, w*4+4); lane l covers float4 l+32*i.
//    2 frames batched -> 6 independent LDG.128 in flight (measured-optimal
//    MLP; 12 regressed via register pressure), then 6 STG.128 with .cs
//    (evict-first streaming -- write-back measured 4.4us slower e2e).
//  - 113MB traffic / 18.9us ~= 6.0 TB/s sustained mixed rw = memory floor;
//    all SM-side pipes slack (issue 16%, alu 8%).
// ---------------------------------------------------------------------------
__global__ void __launch_bounds__(NTHR)
lr_fused(const float4* __restrict__ x, const int* __restrict__ dur,
         float* __restrict__ out, int mode) {
    __shared__ int wsum[NWARP];
    __shared__ int fidx[FPBLK];   // frame -> token index for this window, -1 = zero
    __shared__ int s_mel;

    const int b    = blockIdx.x / BPB;
    const int blk  = blockIdx.x - b * BPB;
    const int t    = threadIdx.x;
    const int lane = t & 31;
    const int w    = t >> 5;

    // ---- inclusive scan of durations: warp shuffle + warp-total fixup ----
    const int v = __ldg(&dur[b * TT + t]);
    int sc = v;
    #pragma unroll
    for (int o = 1; o < 32; o <<= 1) {
        int n = __shfl_up_sync(0xffffffffu, sc, o);
        if (lane >= o) sc += n;
    }
    if (lane == 31) wsum[w] = sc;
    if (t < FPBLK) fidx[t] = -1;
    __syncthreads();
    if (w == 0 && lane < NWARP) {
        int ws = wsum[lane];
        #pragma unroll
        for (int o = 1; o < NWARP; o <<= 1) {
            int n = __shfl_up_sync(0x0000ffffu, ws, o);
            if (lane >= o) ws += n;
        }
        wsum[lane] = ws;
        if (lane == NWARP - 1) s_mel = ws;   // total = mel_len
    }
    __syncthreads();

    const int end   = sc + (w ? wsum[w - 1] : 0);   // inclusive cum[t]
    const int start = end - v;                       // cum[t-1]
    const int mel   = s_mel;
    const int lim   = mel < MAXLEN ? mel : MAXLEN;
    const int f0    = blk * FPBLK;

    // ---- scatter inversion into this block's window (proven semantics) ----
    {
        const int e2 = end < lim ? end : lim;
        int a  = start > f0 ? start : f0;
        int bd = e2 < (f0 + FPBLK) ? e2 : (f0 + FPBLK);
        for (int f = a; f < bd; ++f) fidx[f - f0] = t;        // durations < 8
    }

    // mel_len tail (output 1), written once per batch by block 0
    if (blk == 0 && t == 0 && mode) {
        const long long base = (long long)BB * MAXLEN * DD;
        if (mode == 1)      out[base + b] = (float)mel;
        else                ((long long*)(out + base))[b] = (long long)mel;
    }
    __syncthreads();

    // ---- gather + streaming store: warp-per-frame, 2 frames in flight ----
    const float4* xb = x + (size_t)b * TT * D4;
    float4* ob = (float4*)((float*)out) + ((size_t)b * MAXLEN + f0) * D4;
    const int fr0 = w * FPW;                 // this warp's first frame

    #pragma unroll
    for (int p = 0; p < FPW; p += 2) {       // 2 frames per batch (MLP = 6)
        const int fA = fr0 + p;
        const int fB = fr0 + p + 1;
        const int idA = fidx[fA];            // uniform per warp (broadcast)
        const int idB = fidx[fB];
        float4 valA[ITER], valB[ITER];
        #pragma unroll
        for (int i = 0; i < ITER; ++i) {
            valA[i] = make_float4(0.f, 0.f, 0.f, 0.f);
            if (idA >= 0) valA[i] = __ldg(&xb[idA * D4 + lane + 32 * i]);
        }
        #pragma unroll
        for (int i = 0; i < ITER; ++i) {
            valB[i] = make_float4(0.f, 0.f, 0.f, 0.f);
            if (idB >= 0) valB[i] = __ldg(&xb[idB * D4 + lane + 32 * i]);
        }
        #pragma unroll
        for (int i = 0; i < ITER; ++i)
            __stcs(&ob[fA * D4 + lane + 32 * i], valA[i]);
        #pragma unroll
        for (int i = 0; i < ITER; ++i)
            __stcs(&ob[fB * D4 + lane + 32 * i], valB[i]);
    }
}

extern "C" void kernel_launch(void* const* d_in, const int* in_sizes, int n_in,
                              void* d_out, int out_size) {
    const float* x   = (const float*)d_in[0];
    const int*   dur = (const int*)d_in[1];   // int32 (JAX x64 disabled)

    const long long base = (long long)BB * MAXLEN * DD;   // 25,165,824 f32
    int mode = 0;
    if ((long long)out_size == base + BB)            mode = 1;  // mel as f32
    else if ((long long)out_size == base + 2 * BB)   mode = 2;  // mel as i64

    lr_fused<<<BB * BPB, NTHR>>>((const float4*)x, dur, (float*)d_out, mode);
}

// round 16
// speedup vs baseline: 1.4694x; 1.0516x over previous
#include <cuda_runtime.h>
#include <cuda_bf16.h>

// Problem constants (fixed by the dataset)
#define BB 16
#define TT 512
#define DD 384
#define D4 (DD / 4)          // 96 float4 per row
#define MAXLEN 4096
#define NTHR 512
#define NWARP (NTHR / 32)    // 16
#define FPBLK 64             // frames per block
#define BPB (MAXLEN / FPBLK) // 64 blocks per batch -> grid = 1024
#define FPW (FPBLK / NWARP)  // 4 frames per warp
#define ITER (D4 / 32)       // 3 float4 per lane per frame

// ---------------------------------------------------------------------------
// FINAL kernel — measured optimum (best draw 18.9us; mean ~19.5us, at the
// mixed read/write DRAM drain floor: 113MB / 19us ~= 6 TB/s sustained).
//  - single fused launch: warp-shuffle inclusive scan of durations,
//    scatter inversion (token t owns frames [cum[t-1], min(cum[t], lim))),
//    warp-per-frame gather + .cs streaming stores.
//  - MLP=6 (2 frames x 3 LDG.128 in flight) measured-optimal: 4 worse, 12
//    collapses (register pressure). Write-back stores +4.4us; TMA bulk +11us.
//  - All SM-side pipes slack (issue 16%, alu 8%) -> no SM-side lever remains.
// ---------------------------------------------------------------------------
__global__ void __launch_bounds__(NTHR)
lr_fused(const float4* __restrict__ x, const int* __restrict__ dur,
         float* __restrict__ out, int mode) {
    __shared__ int wsum[NWARP];
    __shared__ int fidx[FPBLK];   // frame -> token index for this window, -1 = zero
    __shared__ int s_mel;

    const int b    = blockIdx.x / BPB;
    const int blk  = blockIdx.x - b * BPB;
    const int t    = threadIdx.x;
    const int lane = t & 31;
    const int w    = t >> 5;

    // ---- inclusive scan of durations: warp shuffle + warp-total fixup ----
    const int v = __ldg(&dur[b * TT + t]);
    int sc = v;
    #pragma unroll
    for (int o = 1; o < 32; o <<= 1) {
        int n = __shfl_up_sync(0xffffffffu, sc, o);
        if (lane >= o) sc += n;
    }
    if (lane == 31) wsum[w] = sc;
    if (t < FPBLK) fidx[t] = -1;
    __syncthreads();
    if (w == 0 && lane < NWARP) {
        int ws = wsum[lane];
        #pragma unroll
        for (int o = 1; o < NWARP; o <<= 1) {
            int n = __shfl_up_sync(0x0000ffffu, ws, o);
            if (lane >= o) ws += n;
        }
        wsum[lane] = ws;
        if (lane == NWARP - 1) s_mel = ws;   // total = mel_len
    }
    __syncthreads();

    const int end   = sc + (w ? wsum[w - 1] : 0);   // inclusive cum[t]
    const int start = end - v;                       // cum[t-1]
    const int mel   = s_mel;
    const int lim   = mel < MAXLEN ? mel : MAXLEN;
    const int f0    = blk * FPBLK;

    // ---- scatter inversion into this block's window (proven semantics) ----
    {
        const int e2 = end < lim ? end : lim;
        int a  = start > f0 ? start : f0;
        int bd = e2 < (f0 + FPBLK) ? e2 : (f0 + FPBLK);
        for (int f = a; f < bd; ++f) fidx[f - f0] = t;        // durations < 8
    }

    // mel_len tail (output 1), written once per batch by block 0
    if (blk == 0 && t == 0 && mode) {
        const long long base = (long long)BB * MAXLEN * DD;
        if (mode == 1)      out[base + b] = (float)mel;
        else                ((long long*)(out + base))[b] = (long long)mel;
    }
    __syncthreads();

    // ---- gather + streaming store: warp-per-frame, 2 frames in flight ----
    const float4* xb = x + (size_t)b * TT * D4;
    float4* ob = (float4*)((float*)out) + ((size_t)b * MAXLEN + f0) * D4;
    const int fr0 = w * FPW;                 // this warp's first frame

    #pragma unroll
    for (int p = 0; p < FPW; p += 2) {       // 2 frames per batch (MLP = 6)
        const int fA = fr0 + p;
        const int fB = fr0 + p + 1;
        const int idA = fidx[fA];            // uniform per warp (broadcast)
        const int idB = fidx[fB];
        float4 valA[ITER], valB[ITER];
        #pragma unroll
        for (int i = 0; i < ITER; ++i) {
            valA[i] = make_float4(0.f, 0.f, 0.f, 0.f);
            if (idA >= 0) valA[i] = __ldg(&xb[idA * D4 + lane + 32 * i]);
        }
        #pragma unroll
        for (int i = 0; i < ITER; ++i) {
            valB[i] = make_float4(0.f, 0.f, 0.f, 0.f);
            if (idB >= 0) valB[i] = __ldg(&xb[idB * D4 + lane + 32 * i]);
        }
        #pragma unroll
        for (int i = 0; i < ITER; ++i)
            __stcs(&ob[fA * D4 + lane + 32 * i], valA[i]);
        #pragma unroll
        for (int i = 0; i < ITER; ++i)
            __stcs(&ob[fB * D4 + lane + 32 * i], valB[i]);
    }
}

extern "C" void kernel_launch(void* const* d_in, const int* in_sizes, int n_in,
                              void* d_out, int out_size) {
    const float* x   = (const float*)d_in[0];
    const int*   dur = (const int*)d_in[1];   // int32 (JAX x64 disabled)

    const long long base = (long long)BB * MAXLEN * DD;   // 25,165,824 f32
    int mode = 0;
    if ((long long)out_size == base + BB)            mode = 1;  // mel as f32
    else if ((long long)out_size == base + 2 * BB)   mode = 2;  // mel as i64

    lr_fused<<<BB * BPB, NTHR>>>((const float4*)x, dur, (float*)d_out, mode);
}

// round 17
// speedup vs baseline: 1.5415x; 1.0491x over previous
#include <cuda_runtime.h>
#include <cuda_bf16.h>

// Problem constants (fixed by the dataset)
#define BB 16
#define TT 512
#define DD 384
#define D4 (DD / 4)          // 96 float4 per row
#define MAXLEN 4096
#define NTHR 512
#define NWARP (NTHR / 32)    // 16
#define FPBLK 32             // frames per block (finer: grid 2048, 13.8/SM)
#define BPB (MAXLEN / FPBLK) // 128 blocks per batch -> grid = 2048
#define FPW (FPBLK / NWARP)  // 2 frames per warp
#define ITER (D4 / 32)       // 3 float4 per lane per frame

// ---------------------------------------------------------------------------
// R16 probe: identical to the measured-best R12 kernel except FPBLK 64->32
// (grid 1024->2048) to shrink the end-of-kernel imbalance quantum from ~14%
// to ~7%. Scan, scatter inversion, warp-per-frame gather, MLP=6, .cs stores
// all byte-identical in structure.
// ---------------------------------------------------------------------------
__global__ void __launch_bounds__(NTHR)
lr_fused(const float4* __restrict__ x, const int* __restrict__ dur,
         float* __restrict__ out, int mode) {
    __shared__ int wsum[NWARP];
    __shared__ int fidx[FPBLK];   // frame -> token index for this window, -1 = zero
    __shared__ int s_mel;

    const int b    = blockIdx.x / BPB;
    const int blk  = blockIdx.x - b * BPB;
    const int t    = threadIdx.x;
    const int lane = t & 31;
    const int w    = t >> 5;

    // ---- inclusive scan of durations: warp shuffle + warp-total fixup ----
    const int v = __ldg(&dur[b * TT + t]);
    int sc = v;
    #pragma unroll
    for (int o = 1; o < 32; o <<= 1) {
        int n = __shfl_up_sync(0xffffffffu, sc, o);
        if (lane >= o) sc += n;
    }
    if (lane == 31) wsum[w] = sc;
    if (t < FPBLK) fidx[t] = -1;
    __syncthreads();
    if (w == 0 && lane < NWARP) {
        int ws = wsum[lane];
        #pragma unroll
        for (int o = 1; o < NWARP; o <<= 1) {
            int n = __shfl_up_sync(0x0000ffffu, ws, o);
            if (lane >= o) ws += n;
        }
        wsum[lane] = ws;
        if (lane == NWARP - 1) s_mel = ws;   // total = mel_len
    }
    __syncthreads();

    const int end   = sc + (w ? wsum[w - 1] : 0);   // inclusive cum[t]
    const int start = end - v;                       // cum[t-1]
    const int mel   = s_mel;
    const int lim   = mel < MAXLEN ? mel : MAXLEN;
    const int f0    = blk * FPBLK;

    // ---- scatter inversion into this block's window (proven semantics) ----
    {
        const int e2 = end < lim ? end : lim;
        int a  = start > f0 ? start : f0;
        int bd = e2 < (f0 + FPBLK) ? e2 : (f0 + FPBLK);
        for (int f = a; f < bd; ++f) fidx[f - f0] = t;        // durations < 8
    }

    // mel_len tail (output 1), written once per batch by block 0
    if (blk == 0 && t == 0 && mode) {
        const long long base = (long long)BB * MAXLEN * DD;
        if (mode == 1)      out[base + b] = (float)mel;
        else                ((long long*)(out + base))[b] = (long long)mel;
    }
    __syncthreads();

    // ---- gather + streaming store: warp-per-frame, 2 frames in flight ----
    const float4* xb = x + (size_t)b * TT * D4;
    float4* ob = (float4*)((float*)out) + ((size_t)b * MAXLEN + f0) * D4;
    const int fr0 = w * FPW;                 // this warp's first frame

    #pragma unroll
    for (int p = 0; p < FPW; p += 2) {       // 2 frames per batch (MLP = 6)
        const int fA = fr0 + p;
        const int fB = fr0 + p + 1;
        const int idA = fidx[fA];            // uniform per warp (broadcast)
        const int idB = fidx[fB];
        float4 valA[ITER], valB[ITER];
        #pragma unroll
        for (int i = 0; i < ITER; ++i) {
            valA[i] = make_float4(0.f, 0.f, 0.f, 0.f);
            if (idA >= 0) valA[i] = __ldg(&xb[idA * D4 + lane + 32 * i]);
        }
        #pragma unroll
        for (int i = 0; i < ITER; ++i) {
            valB[i] = make_float4(0.f, 0.f, 0.f, 0.f);
            if (idB >= 0) valB[i] = __ldg(&xb[idB * D4 + lane + 32 * i]);
        }
        #pragma unroll
        for (int i = 0; i < ITER; ++i)
            __stcs(&ob[fA * D4 + lane + 32 * i], valA[i]);
        #pragma unroll
        for (int i = 0; i < ITER; ++i)
            __stcs(&ob[fB * D4 + lane + 32 * i], valB[i]);
    }
}

extern "C" void kernel_launch(void* const* d_in, const int* in_sizes, int n_in,
                              void* d_out, int out_size) {
    const float* x   = (const float*)d_in[0];
    const int*   dur = (const int*)d_in[1];   // int32 (JAX x64 disabled)

    const long long base = (long long)BB * MAXLEN * DD;   // 25,165,824 f32
    int mode = 0;
    if ((long long)out_size == base + BB)            mode = 1;  // mel as f32
    else if ((long long)out_size == base + 2 * BB)   mode = 2;  // mel as i64

    lr_fused<<<BB * BPB, NTHR>>>((const float4*)x, dur, (float*)d_out, mode);
}